// round 8
// baseline (speedup 1.0000x reference)
#include <cuda_runtime.h>
#include <cuda_fp16.h>
#include <math.h>
#include <stdint.h>

#define HIN     14
#define WIN     14
#define HO      12
#define WO      12
#define BATCH   4
#define FIN     32
#define DIN     8
#define FF      32
#define CCAP    288
#define DOUT    16
#define NPOS    (BATCH*HO*WO)   // 576

// pass1: 8 warps, 6 pos/warp -> 48 pos/CTA; 12 c-chunks of 24; grid 12x12=144
#define TPB     256
#define POSB1   48
#define NPB1    (NPOS/POSB1)    // 12
#define NCH1    12
#define CPC1    (CCAP/NCH1)     // 24 (6 quartets)

// pass2: 8 warps, 4 pos/warp -> 32 pos/CTA; 8 c-chunks of 36; grid 18x8=144
#define POSB2   32
#define NPB2    (NPOS/POSB2)    // 18
#define NCH2    8
#define CPC2    (CCAP/NCH2)     // 36 (9 quartets)

#define SMEM_BYTES (8 * 2048 * 8)   // 8 stages x 16KB = 128KB

typedef unsigned long long u64;

// ---------------- scratch (static device globals) ---------------------------
__device__ float2   g_Wtp[(size_t)CCAP*8*8*32];               // [c][i][p][f] f32x2 pairs
__device__ float2   g_S1p[(size_t)NCH1*NPOS*FF*8];            // pass1 partials
__device__ uint32_t g_out1h[(size_t)NPOS*FF*8];               // squash(iter1) as half2 pairs
__device__ float2   g_centp[(size_t)NCH2*NPOS*FF*8];          // pass2 partial centroids

__device__ __constant__ int c_koff[9] = {0, 256, 512, 3584, 3840, 4096, 7168, 7424, 7680};

// ---------------- f32x2 helpers ---------------------------------------------
__device__ __forceinline__ u64 pk(float lo, float hi) {
    u64 r; asm("mov.b64 %0,{%1,%2};" : "=l"(r) : "f"(lo), "f"(hi)); return r;
}
__device__ __forceinline__ void upk(u64 v, float& a, float& b) {
    asm("mov.b64 {%0,%1},%2;" : "=f"(a), "=f"(b) : "l"(v));
}
__device__ __forceinline__ u64 fma2(u64 a, u64 b, u64 c) {
    u64 d; asm("fma.rn.f32x2 %0,%1,%2,%3;" : "=l"(d) : "l"(a), "l"(b), "l"(c)); return d;
}

// ---------------- cp.async helpers -------------------------------------------
__device__ __forceinline__ void cp16(uint32_t saddr, const void* gaddr) {
    asm volatile("cp.async.cg.shared.global [%0], [%1], 16;" :: "r"(saddr), "l"(gaddr));
}
__device__ __forceinline__ void stage_copy(u64* sdst, const float2* gsrc, int tid) {
    uint32_t s = (uint32_t)__cvta_generic_to_shared(sdst);
    const char* g = (const char*)gsrc;
    #pragma unroll
    for (int k = 0; k < 4; ++k) {          // 4 * 256 = 1024 x 16B
        int idx = tid + k * TPB;
        cp16(s + idx * 16, g + (size_t)idx * 16);
    }
    asm volatile("cp.async.commit_group;");
}
template<int N>
__device__ __forceinline__ void wait_cp() {
    asm volatile("cp.async.wait_group %0;" :: "n"(N));
}

// ---------------- W transform: W[f][c][o][i] -> Wtp[c][i][p][f] pairs --------
__global__ void k_transpose(const float* __restrict__ W) {
    int tid = blockIdx.x * blockDim.x + threadIdx.x;
    if (tid >= CCAP * 8 * 32) return;
    int f = tid & 31;
    int r = tid >> 5;
    int p = r & 7;
    int c = r >> 3;
    const float* row0 = W + (((size_t)f * CCAP + c) * DOUT + p) * DIN;
    const float* row8 = W + (((size_t)f * CCAP + c) * DOUT + p + 8) * DIN;
    float4 a0 = ((const float4*)row0)[0], a1 = ((const float4*)row0)[1];
    float4 b0 = ((const float4*)row8)[0], b1 = ((const float4*)row8)[1];
    float a[8] = {a0.x,a0.y,a0.z,a0.w,a1.x,a1.y,a1.z,a1.w};
    float b[8] = {b0.x,b0.y,b0.z,b0.w,b1.x,b1.y,b1.z,b1.w};
    #pragma unroll
    for (int i = 0; i < 8; ++i)
        g_Wtp[(((size_t)c * 8 + i) * 8 + p) * 32 + f] = make_float2(a[i], b[i]);
}

__device__ __forceinline__ const float* pos_base(const float* x, int pos) {
    int b = pos / (HO * WO);
    int r = pos % (HO * WO);
    int h = r / WO;
    int w = r % WO;
    return x + (((size_t)(b * HIN + h) * WIN) + w) * (FIN * DIN);
}

// ---------------- pass 1: partial sum over c of preds (6 pos/warp) ----------
__global__ void __launch_bounds__(TPB, 1) k_pass1(const float* __restrict__ x) {
    extern __shared__ u64 sW[];   // 8 stages x 2048 u64
    int tid  = threadIdx.x;
    int lane = tid & 31;
    int w    = tid >> 5;
    int pos0 = blockIdx.x * POSB1 + w * 6;
    int cch  = blockIdx.y;
    int cbeg = cch * CPC1;
    const int NT = CPC1 / 4;   // 6 quartets

    const float* xb[6];
    #pragma unroll
    for (int q = 0; q < 6; ++q) xb[q] = pos_base(x, pos0 + q);

    u64 acc[6][8];
    #pragma unroll
    for (int q = 0; q < 6; ++q)
        #pragma unroll
        for (int p = 0; p < 8; ++p) acc[q][p] = 0ULL;

    #pragma unroll
    for (int j = 0; j < 4; ++j)
        stage_copy(sW + (size_t)j * 2048, g_Wtp + (size_t)(cbeg + j) * 2048, tid);
    #pragma unroll
    for (int j = 0; j < 4; ++j)
        stage_copy(sW + (size_t)(4 + j) * 2048, g_Wtp + (size_t)(cbeg + 4 + j) * 2048, tid);

    for (int t = 0; t < NT; ++t) {
        if (t + 1 < NT) wait_cp<4>(); else wait_cp<0>();
        __syncthreads();
        int sset = (t & 1) * 4;
        int qbeg = cbeg + t * 4;

        #pragma unroll
        for (int k = 0; k < 4; ++k) {
            int j = (w + k) & 3;          // rotated order per warp
            int c = qbeg + j;
            int off = c_koff[c >> 5] + (c & 31) * DIN;
            float xs[6][8];
            #pragma unroll
            for (int q = 0; q < 6; ++q) {
                float4 v0 = ((const float4*)(xb[q] + off))[0];
                float4 v1 = ((const float4*)(xb[q] + off))[1];
                xs[q][0]=v0.x; xs[q][1]=v0.y; xs[q][2]=v0.z; xs[q][3]=v0.w;
                xs[q][4]=v1.x; xs[q][5]=v1.y; xs[q][6]=v1.z; xs[q][7]=v1.w;
            }
            const u64* wb = sW + (size_t)(sset + j) * 2048;
            #pragma unroll
            for (int i = 0; i < 8; ++i) {
                u64 xd[6];
                #pragma unroll
                for (int q = 0; q < 6; ++q) xd[q] = pk(xs[q][i], xs[q][i]);
                #pragma unroll
                for (int p = 0; p < 8; ++p) {
                    u64 wv = wb[(i * 8 + p) * 32 + lane];
                    #pragma unroll
                    for (int q = 0; q < 6; ++q)
                        acc[q][p] = fma2(wv, xd[q], acc[q][p]);
                }
            }
        }

        __syncthreads();
        if (t + 2 < NT) {
            #pragma unroll
            for (int j = 0; j < 4; ++j)
                stage_copy(sW + (size_t)(sset + j) * 2048,
                           g_Wtp + (size_t)(cbeg + (t + 2) * 4 + j) * 2048, tid);
        }
    }

    #pragma unroll
    for (int q = 0; q < 6; ++q) {
        u64* d = (u64*)g_S1p + (((size_t)cch * NPOS + pos0 + q) * FF + lane) * 8;
        #pragma unroll
        for (int p = 0; p < 8; ++p) d[p] = acc[q][p];
    }
}

// ---------------- squash 1: half2-packed out1 --------------------------------
__global__ void k_squash1() {
    int t = blockIdx.x * blockDim.x + threadIdx.x;   // (pos,f)
    if (t >= NPOS * FF) return;
    float sx[8], sy[8];
    #pragma unroll
    for (int p = 0; p < 8; ++p) { sx[p] = 0.f; sy[p] = 0.f; }
    for (int ch = 0; ch < NCH1; ++ch) {
        const float2* s = g_S1p + ((size_t)ch * NPOS * FF + t) * 8;
        #pragma unroll
        for (int p = 0; p < 8; ++p) { float2 v = s[p]; sx[p] += v.x; sy[p] += v.y; }
    }
    float sn = 0.f;
    #pragma unroll
    for (int p = 0; p < 8; ++p) {
        sx[p] *= (1.f / 32.f); sy[p] *= (1.f / 32.f);
        sn += sx[p] * sx[p] + sy[p] * sy[p];
    }
    float sc = (sn / (1.f + sn)) / sqrtf(sn + 1e-7f);
    uint32_t* d = g_out1h + (size_t)t * 8;
    #pragma unroll
    for (int p = 0; p < 8; ++p) {
        __half2 h = __floats2half2_rn(sx[p] * sc, sy[p] * sc);
        d[p] = *reinterpret_cast<uint32_t*>(&h);
    }
}

// ---------------- pass 2: fused agreement/softmax(F)/centroid (4 pos/warp) --
__global__ void __launch_bounds__(TPB, 1) k_pass2(const float* __restrict__ x) {
    extern __shared__ u64 sW[];   // 8 stages x 2048 u64
    int tid  = threadIdx.x;
    int lane = tid & 31;
    int w    = tid >> 5;
    int pos0 = blockIdx.x * POSB2 + w * 4;
    int cch  = blockIdx.y;
    int cbeg = cch * CPC2;
    const int NT = CPC2 / 4;   // 9 quartets

    const float* xb[4];
    #pragma unroll
    for (int q = 0; q < 4; ++q) xb[q] = pos_base(x, pos0 + q);

    // out1 packed as half2 pairs: 8 u32 per position (register diet)
    uint32_t o1h[4][8];
    #pragma unroll
    for (int q = 0; q < 4; ++q) {
        const uint32_t* s = g_out1h + (((size_t)(pos0 + q) * FF) + lane) * 8;
        #pragma unroll
        for (int p = 0; p < 8; ++p) o1h[q][p] = s[p];
    }

    u64 ce[4][8];
    #pragma unroll
    for (int q = 0; q < 4; ++q)
        #pragma unroll
        for (int p = 0; p < 8; ++p) ce[q][p] = 0ULL;

    #pragma unroll
    for (int j = 0; j < 4; ++j)
        stage_copy(sW + (size_t)j * 2048, g_Wtp + (size_t)(cbeg + j) * 2048, tid);
    #pragma unroll
    for (int j = 0; j < 4; ++j)
        stage_copy(sW + (size_t)(4 + j) * 2048, g_Wtp + (size_t)(cbeg + 4 + j) * 2048, tid);

    for (int t = 0; t < NT; ++t) {
        if (t + 1 < NT) wait_cp<4>(); else wait_cp<0>();
        __syncthreads();
        int sset = (t & 1) * 4;
        int qbeg = cbeg + t * 4;

        #pragma unroll
        for (int k = 0; k < 4; ++k) {
            int j = (w + k) & 3;          // rotated order per warp -> phase mixing
            int c = qbeg + j;
            int off = c_koff[c >> 5] + (c & 31) * DIN;
            float xs[4][8];
            #pragma unroll
            for (int q = 0; q < 4; ++q) {
                float4 v0 = ((const float4*)(xb[q] + off))[0];
                float4 v1 = ((const float4*)(xb[q] + off))[1];
                xs[q][0]=v0.x; xs[q][1]=v0.y; xs[q][2]=v0.z; xs[q][3]=v0.w;
                xs[q][4]=v1.x; xs[q][5]=v1.y; xs[q][6]=v1.z; xs[q][7]=v1.w;
            }

            u64 pr[4][8];
            #pragma unroll
            for (int q = 0; q < 4; ++q)
                #pragma unroll
                for (int p = 0; p < 8; ++p) pr[q][p] = 0ULL;

            const u64* wb = sW + (size_t)(sset + j) * 2048;
            #pragma unroll
            for (int i = 0; i < 8; ++i) {
                u64 xd0 = pk(xs[0][i], xs[0][i]);
                u64 xd1 = pk(xs[1][i], xs[1][i]);
                u64 xd2 = pk(xs[2][i], xs[2][i]);
                u64 xd3 = pk(xs[3][i], xs[3][i]);
                #pragma unroll
                for (int p = 0; p < 8; ++p) {
                    u64 wv = wb[(i * 8 + p) * 32 + lane];
                    pr[0][p] = fma2(wv, xd0, pr[0][p]);
                    pr[1][p] = fma2(wv, xd1, pr[1][p]);
                    pr[2][p] = fma2(wv, xd2, pr[2][p]);
                    pr[3][p] = fma2(wv, xd3, pr[3][p]);
                }
            }

            // agreement dots: unpack half2 out1 -> fp32 pair, packed fma
            float e[4];
            #pragma unroll
            for (int q = 0; q < 4; ++q) {
                u64 a = 0ULL;
                #pragma unroll
                for (int p = 0; p < 8; ++p) {
                    __half2 h = *reinterpret_cast<const __half2*>(&o1h[q][p]);
                    float2 f = __half22float2(h);
                    a = fma2(pr[q][p], pk(f.x, f.y), a);
                }
                float l, hh;
                upk(a, l, hh);
                e[q] = __expf(l + hh);   // no max-subtraction: |agreement| is O(1)
            }

            // 4 independent butterfly sums over f (lanes)
            float s0 = e[0], s1 = e[1], s2 = e[2], s3 = e[3];
            #pragma unroll
            for (int d = 16; d > 0; d >>= 1) {
                s0 += __shfl_xor_sync(0xffffffffu, s0, d);
                s1 += __shfl_xor_sync(0xffffffffu, s1, d);
                s2 += __shfl_xor_sync(0xffffffffu, s2, d);
                s3 += __shfl_xor_sync(0xffffffffu, s3, d);
            }
            float cc[4] = { __fdividef(e[0], s0), __fdividef(e[1], s1),
                            __fdividef(e[2], s2), __fdividef(e[3], s3) };

            #pragma unroll
            for (int q = 0; q < 4; ++q) {
                u64 cd = pk(cc[q], cc[q]);
                #pragma unroll
                for (int p = 0; p < 8; ++p)
                    ce[q][p] = fma2(pr[q][p], cd, ce[q][p]);
            }
        }

        __syncthreads();
        if (t + 2 < NT) {
            #pragma unroll
            for (int j = 0; j < 4; ++j)
                stage_copy(sW + (size_t)(sset + j) * 2048,
                           g_Wtp + (size_t)(cbeg + (t + 2) * 4 + j) * 2048, tid);
        }
    }

    #pragma unroll
    for (int q = 0; q < 4; ++q) {
        u64* d = (u64*)g_centp + (((size_t)cch * NPOS + pos0 + q) * FF + lane) * 8;
        #pragma unroll
        for (int p = 0; p < 8; ++p) d[p] = ce[q][p];
    }
}

// ---------------- squash 2: final output ------------------------------------
__global__ void k_squash2(float* __restrict__ out) {
    int t = blockIdx.x * blockDim.x + threadIdx.x;   // (pos,f)
    if (t >= NPOS * FF) return;
    float sx[8], sy[8];
    #pragma unroll
    for (int p = 0; p < 8; ++p) { sx[p] = 0.f; sy[p] = 0.f; }
    for (int ch = 0; ch < NCH2; ++ch) {
        const float2* s = g_centp + ((size_t)ch * NPOS * FF + t) * 8;
        #pragma unroll
        for (int p = 0; p < 8; ++p) { float2 v = s[p]; sx[p] += v.x; sy[p] += v.y; }
    }
    float sn = 0.f;
    #pragma unroll
    for (int p = 0; p < 8; ++p) sn += sx[p] * sx[p] + sy[p] * sy[p];
    float sc = (sn / (1.f + sn)) / sqrtf(sn + 1e-7f);
    float* d = out + (size_t)t * DOUT;
    #pragma unroll
    for (int p = 0; p < 8; ++p) { d[p] = sx[p] * sc; d[p + 8] = sy[p] * sc; }
}

// -----------------------------------------------------------------------------
extern "C" void kernel_launch(void* const* d_in, const int* in_sizes, int n_in,
                              void* d_out, int out_size) {
    const float* x = (const float*)d_in[0];
    const float* W = (const float*)d_in[1];
    if (n_in >= 2 && in_sizes[0] == (int)((size_t)FF * CCAP * DOUT * DIN)) {
        const float* t = x; x = W; W = t;
    }
    float* out = (float*)d_out;

    cudaFuncSetAttribute(k_pass1, cudaFuncAttributeMaxDynamicSharedMemorySize, SMEM_BYTES);
    cudaFuncSetAttribute(k_pass2, cudaFuncAttributeMaxDynamicSharedMemorySize, SMEM_BYTES);

    k_transpose<<<(CCAP * 8 * 32 + 255) / 256, 256>>>(W);
    k_pass1<<<dim3(NPB1, NCH1), TPB, SMEM_BYTES>>>(x);
    k_squash1<<<(NPOS * FF + 255) / 256, 256>>>();
    k_pass2<<<dim3(NPB2, NCH2), TPB, SMEM_BYTES>>>(x);
    k_squash2<<<(NPOS * FF + 255) / 256, 256>>>(out);
}